// round 1
// baseline (speedup 1.0000x reference)
#include <cuda_runtime.h>
#include <math.h>

#define Bsz 128
#define Nn  512
#define Ff  64
#define Dd  64
#define Kk  20
#define BN  (Bsz*Nn)          // 65536
#define NELEM (BN*Dd)         // 4194304
#define STAT_BLOCKS 1024

// ---------------- device scratch (no allocations allowed) ----------------
__device__ float d_g[NELEM];
__device__ float d_agg[NELEM];
__device__ float d_h1[NELEM];
__device__ float d_enorm[Nn*Dd];
__device__ float d_si[BN];
__device__ float d_sj[BN];
__device__ float d_eai[Nn];
__device__ float d_eaj[Nn];
__device__ int   d_topk[Nn*Kk];
__device__ float d_psum[STAT_BLOCKS*64];
__device__ float d_psq [STAT_BLOCKS*64];
__device__ float d_scale1[64], d_shift1[64], d_scale2[64], d_shift2[64];

__device__ __forceinline__ float warpSum(float v){
  #pragma unroll
  for(int o=16;o;o>>=1) v += __shfl_xor_sync(0xffffffffu, v, o);
  return v;
}
__device__ __forceinline__ float warpMax(float v){
  #pragma unroll
  for(int o=16;o;o>>=1) v = fmaxf(v, __shfl_xor_sync(0xffffffffu, v, o));
  return v;
}

// ---- K1: normalize embed rows, per-node embed-attention scalars ----
__global__ void k_embed(const float* __restrict__ embed,
                        const float* __restrict__ aemi,
                        const float* __restrict__ aemj){
  int gw   = (blockIdx.x*blockDim.x + threadIdx.x) >> 5;
  int lane = threadIdx.x & 31;
  if(gw >= Nn) return;
  float v0 = embed[gw*64+lane];
  float v1 = embed[gw*64+32+lane];
  float ss = warpSum(v0*v0 + v1*v1);
  float inv = 1.0f/(sqrtf(ss)+1e-12f);
  d_enorm[gw*64+lane]    = v0*inv;
  d_enorm[gw*64+32+lane] = v1*inv;
  float si = warpSum(v0*aemi[lane] + v1*aemi[lane+32]);
  float sj = warpSum(v0*aemj[lane] + v1*aemj[lane+32]);
  if(lane==0){ d_eai[gw]=si; d_eaj[gw]=sj; }
}

// ---- K2: cosine similarity + top-K per node (block per node) ----
__global__ void k_topk(){
  __shared__ float sims[Nn];
  __shared__ float srow[64];
  __shared__ float rv[256];
  __shared__ int   ri[256];
  int i = blockIdx.x, t = threadIdx.x;
  if(t < 64) srow[t] = d_enorm[i*64+t];
  __syncthreads();
  for(int j=t; j<Nn; j+=256){
    const float* er = &d_enorm[j*64];
    float s = 0.f;
    #pragma unroll
    for(int k=0;k<64;k++) s += srow[k]*er[k];
    sims[j] = s;
  }
  __syncthreads();
  for(int sel=0; sel<Kk; sel++){
    float bv = -INFINITY; int bi = 0x7fffffff;
    for(int j=t; j<Nn; j+=256){
      float v = sims[j];
      if(v > bv || (v == bv && j < bi)){ bv = v; bi = j; }
    }
    rv[t]=bv; ri[t]=bi;
    __syncthreads();
    for(int s=128; s>0; s>>=1){
      if(t < s){
        float ov = rv[t+s]; int oi = ri[t+s];
        if(ov > rv[t] || (ov == rv[t] && oi < ri[t])){ rv[t]=ov; ri[t]=oi; }
      }
      __syncthreads();
    }
    if(t==0){ d_topk[i*Kk+sel] = ri[0]; sims[ri[0]] = -INFINITY; }
    __syncthreads();
  }
}

// ---- K3: g = x @ W_lin, plus per-row attention scores s_i, s_j ----
// warp per row; W^T in shared (stride 68 -> conflict-free float4 reads)
__global__ void k_gemm(const float* __restrict__ x, const float* __restrict__ W,
                       const float* __restrict__ ati, const float* __restrict__ atj){
  __shared__ float Wt[64*68];
  __shared__ float sai[64], saj[64];
  int t = threadIdx.x;
  for(int idx=t; idx<4096; idx+=256){
    int k = idx>>6, c = idx&63;
    Wt[c*68+k] = W[idx];
  }
  if(t < 64){ sai[t]=ati[t]; saj[t]=atj[t]; }
  __syncthreads();
  int lane = t&31, w = t>>5;
  int row  = blockIdx.x*8 + w;
  const float* xr = x + row*64;
  float xv0 = xr[lane], xv1 = xr[32+lane];
  float acc0 = 0.f, acc1 = 0.f;
  #pragma unroll
  for(int kk=0; kk<64; kk+=4){
    float xs = (kk < 32) ? xv0 : xv1;
    float b0 = __shfl_sync(0xffffffffu, xs,  kk   &31);
    float b1 = __shfl_sync(0xffffffffu, xs, (kk+1)&31);
    float b2 = __shfl_sync(0xffffffffu, xs, (kk+2)&31);
    float b3 = __shfl_sync(0xffffffffu, xs, (kk+3)&31);
    float4 wa = *reinterpret_cast<const float4*>(&Wt[lane*68+kk]);
    float4 wb = *reinterpret_cast<const float4*>(&Wt[(lane+32)*68+kk]);
    acc0 += b0*wa.x + b1*wa.y + b2*wa.z + b3*wa.w;
    acc1 += b0*wb.x + b1*wb.y + b2*wb.z + b3*wb.w;
  }
  d_g[row*64+lane]    = acc0;
  d_g[row*64+32+lane] = acc1;
  float si = warpSum(acc0*sai[lane] + acc1*sai[lane+32]);
  float sj = warpSum(acc0*saj[lane] + acc1*saj[lane+32]);
  if(lane==0){
    int node = row & (Nn-1);
    d_si[row] = si + d_eai[node];
    d_sj[row] = sj + d_eaj[node];
  }
}

// ---- K4: per-destination softmax over 21 candidate edges + aggregation ----
__global__ void k_attn(const float* __restrict__ gnn_bias){
  int lane = threadIdx.x & 31, w = threadIdx.x >> 5;
  int row  = blockIdx.x*8 + w;
  int b = row >> 9;
  int i = row & (Nn-1);
  int src  = (lane < Kk) ? d_topk[i*Kk+lane] : i;   // lane==20 -> self loop
  int srow = (b << 9) + src;
  float z;
  if(lane <= Kk){
    z = d_si[row] + d_sj[srow];
    z = (z > 0.f) ? z : 0.2f*z;                     // leaky_relu(0.2)
    if(lane < Kk && src == i) z = -INFINITY;        // remove_self_loops
  } else {
    z = -INFINITY;
  }
  float m = warpMax(z);
  float e = (lane <= Kk) ? expf(z - m) : 0.f;
  float s = warpSum(e);
  float attn = e / s;
  float acc0 = 0.f, acc1 = 0.f;
  #pragma unroll
  for(int e2=0; e2<=Kk; e2++){
    float a  = __shfl_sync(0xffffffffu, attn, e2);
    int   sr = __shfl_sync(0xffffffffu, srow, e2);
    const float* gr = &d_g[sr*64];
    acc0 += a*gr[lane];
    acc1 += a*gr[32+lane];
  }
  d_agg[row*64+lane]    = acc0 + gnn_bias[lane];
  d_agg[row*64+32+lane] = acc1 + gnn_bias[lane+32];
}

// ---- K5: deterministic per-channel sum/sumsq partials (which: 0=agg, 1=h1) ----
__global__ void k_stats(int which){
  const float* __restrict__ src = which ? d_h1 : d_agg;
  int t = threadIdx.x;
  float s = 0.f, s2 = 0.f;
  for(int e = blockIdx.x*256 + t; e < NELEM; e += STAT_BLOCKS*256){
    float v = src[e];
    s += v; s2 += v*v;
  }
  __shared__ float sh[256], sh2[256];
  sh[t]=s; sh2[t]=s2;
  __syncthreads();
  if(t < 64){
    // thread t accumulated channel t%64 (stride multiple of 64)
    s  = sh[t]  + sh[t+64]  + sh[t+128]  + sh[t+192];
    s2 = sh2[t] + sh2[t+64] + sh2[t+128] + sh2[t+192];
    d_psum[blockIdx.x*64+t] = s;
    d_psq [blockIdx.x*64+t] = s2;
  }
}

// ---- K6: finalize BN scale/shift (which: 0 -> bn1, 1 -> bn2) ----
__global__ void k_finalize(int which, const float* __restrict__ gamma,
                           const float* __restrict__ beta){
  int t = threadIdx.x;   // 64 threads
  float s = 0.f, s2 = 0.f;
  for(int b2=0; b2<STAT_BLOCKS; b2++){
    s  += d_psum[b2*64+t];
    s2 += d_psq [b2*64+t];
  }
  float mu  = s  * (1.0f/(float)BN);
  float var = s2 * (1.0f/(float)BN) - mu*mu;
  float sc  = gamma[t] * rsqrtf(var + 1e-5f);
  float sh  = beta[t] - mu*sc;
  if(which == 0){ d_scale1[t]=sc; d_shift1[t]=sh; }
  else          { d_scale2[t]=sc; d_shift2[t]=sh; }
}

// ---- K7: h1 = relu(bn1(agg)) * embed (vectorized) ----
__global__ void k_h1(const float* __restrict__ embed){
  int stride = gridDim.x*blockDim.x;
  for(int i = blockIdx.x*blockDim.x + threadIdx.x; i < BN*16; i += stride){
    int row = i >> 4;
    int q   = i & 15;
    int d0  = q*4;
    int node = row & (Nn-1);
    float4 a  = reinterpret_cast<const float4*>(d_agg)[i];
    float4 em = reinterpret_cast<const float4*>(embed)[node*16+q];
    float4 r;
    r.x = fmaxf(a.x*d_scale1[d0+0]+d_shift1[d0+0], 0.f)*em.x;
    r.y = fmaxf(a.y*d_scale1[d0+1]+d_shift1[d0+1], 0.f)*em.y;
    r.z = fmaxf(a.z*d_scale1[d0+2]+d_shift1[d0+2], 0.f)*em.z;
    r.w = fmaxf(a.w*d_scale1[d0+3]+d_shift1[d0+3], 0.f)*em.w;
    reinterpret_cast<float4*>(d_h1)[i] = r;
  }
}

// ---- K8: out = relu(bn2(h1)) @ out_W + out_b ----
__global__ void k_out(const float* __restrict__ outW, const float* __restrict__ outB,
                      float* __restrict__ out){
  int lane = threadIdx.x & 31, w = threadIdx.x >> 5;
  int row  = blockIdx.x*8 + w;
  float v0 = fmaxf(d_h1[row*64+lane]   *d_scale2[lane]   +d_shift2[lane],    0.f)*outW[lane];
  float v1 = fmaxf(d_h1[row*64+32+lane]*d_scale2[lane+32]+d_shift2[lane+32], 0.f)*outW[lane+32];
  float s = warpSum(v0 + v1);
  if(lane==0) out[row] = s + outB[0];
}

extern "C" void kernel_launch(void* const* d_in, const int* in_sizes, int n_in,
                              void* d_out, int out_size){
  // Resolve input ordering: setup_inputs dict order has org_edge_index (2*1024 int32)
  // at slot 1; reference-signature order puts it last.
  int iData, iEmbed, iW, iAtI, iAtJ, iAemI, iAemJ, iBias, iG1, iB1, iG2, iB2, iOW, iOB;
  if(n_in >= 15 && in_sizes[1] == 2048){
    iData=0; iEmbed=2; iW=3; iAtI=4; iAtJ=5; iAemI=6; iAemJ=7; iBias=8;
    iG1=9; iB1=10; iG2=11; iB2=12; iOW=13; iOB=14;
  } else {
    iData=0; iEmbed=1; iW=2; iAtI=3; iAtJ=4; iAemI=5; iAemJ=6; iBias=7;
    iG1=8; iB1=9; iG2=10; iB2=11; iOW=12; iOB=13;
  }
  const float* data  = (const float*)d_in[iData];
  const float* embed = (const float*)d_in[iEmbed];
  const float* W     = (const float*)d_in[iW];
  const float* atI   = (const float*)d_in[iAtI];
  const float* atJ   = (const float*)d_in[iAtJ];
  const float* aemI  = (const float*)d_in[iAemI];
  const float* aemJ  = (const float*)d_in[iAemJ];
  const float* bias  = (const float*)d_in[iBias];
  const float* g1    = (const float*)d_in[iG1];
  const float* b1    = (const float*)d_in[iB1];
  const float* g2    = (const float*)d_in[iG2];
  const float* b2    = (const float*)d_in[iB2];
  const float* outW  = (const float*)d_in[iOW];
  const float* outB  = (const float*)d_in[iOB];
  float* out = (float*)d_out;

  k_embed   <<<64, 256>>>(embed, aemI, aemJ);
  k_topk    <<<Nn, 256>>>();
  k_gemm    <<<BN/8, 256>>>(data, W, atI, atJ);
  k_attn    <<<BN/8, 256>>>(bias);
  k_stats   <<<STAT_BLOCKS, 256>>>(0);
  k_finalize<<<1, 64>>>(0, g1, b1);
  k_h1      <<<1024, 256>>>(embed);
  k_stats   <<<STAT_BLOCKS, 256>>>(1);
  k_finalize<<<1, 64>>>(1, g2, b2);
  k_out     <<<BN/8, 256>>>(outW, outB, out);
}

// round 2
// speedup vs baseline: 2.1794x; 2.1794x over previous
#include <cuda_runtime.h>
#include <math.h>

#define Bsz 128
#define Nn  512
#define Ff  64
#define Dd  64
#define Kk  20
#define BN  (Bsz*Nn)          // 65536
#define NELEM (BN*Dd)         // 4194304
#define ATTN_BLOCKS (BN/8)    // 8192
#define H1_BLOCKS   1024

// ---------------- device scratch (no allocations allowed) ----------------
__device__ float d_g[NELEM];
__device__ float d_agg[NELEM];
__device__ float d_h1[NELEM];
__device__ float d_enorm[Nn*Dd];
__device__ float d_si[BN];
__device__ float d_sj[BN];
__device__ float d_eai[Nn];
__device__ float d_eaj[Nn];
__device__ int   d_topk[Nn*Kk];
__device__ float d_ps1[64*ATTN_BLOCKS];   // channel-major BN1 partial sums
__device__ float d_pq1[64*ATTN_BLOCKS];
__device__ float d_ps2[64*H1_BLOCKS];     // channel-major BN2 partial sums
__device__ float d_pq2[64*H1_BLOCKS];
__device__ float d_scale1[64], d_shift1[64], d_scale2[64], d_shift2[64];

__device__ __forceinline__ float warpSum(float v){
  #pragma unroll
  for(int o=16;o;o>>=1) v += __shfl_xor_sync(0xffffffffu, v, o);
  return v;
}
__device__ __forceinline__ float warpMax(float v){
  #pragma unroll
  for(int o=16;o;o>>=1) v = fmaxf(v, __shfl_xor_sync(0xffffffffu, v, o));
  return v;
}

// ---- K1: normalize embed rows, per-node embed-attention scalars ----
__global__ void k_embed(const float* __restrict__ embed,
                        const float* __restrict__ aemi,
                        const float* __restrict__ aemj){
  int gw   = (blockIdx.x*blockDim.x + threadIdx.x) >> 5;
  int lane = threadIdx.x & 31;
  if(gw >= Nn) return;
  float v0 = embed[gw*64+lane];
  float v1 = embed[gw*64+32+lane];
  float ss = warpSum(v0*v0 + v1*v1);
  float inv = 1.0f/(sqrtf(ss)+1e-12f);
  d_enorm[gw*64+lane]    = v0*inv;
  d_enorm[gw*64+32+lane] = v1*inv;
  float si = warpSum(v0*aemi[lane] + v1*aemi[lane+32]);
  float sj = warpSum(v0*aemj[lane] + v1*aemj[lane+32]);
  if(lane==0){ d_eai[gw]=si; d_eaj[gw]=sj; }
}

// ---- K2: warp-per-node topk. All 512 sims live in registers (16/lane). ----
// grid 64 blocks x 256 threads (8 warps = 8 nodes per block).
__global__ void k_topk(){
  __shared__ float tile[64*68];   // 64 e_norm rows, padded stride 68 (16B-aligned)
  __shared__ float srows[8*68];   // this block's 8 node rows
  int t = threadIdx.x, w = t>>5, lane = t&31;
  int node = blockIdx.x*8 + w;

  // load this block's 8 source rows (512 floats) as float4
  if(t < 128){
    int r = t >> 4, c4 = t & 15;
    float4 v = reinterpret_cast<const float4*>(d_enorm)[(blockIdx.x*8 + r)*16 + c4];
    *reinterpret_cast<float4*>(&srows[r*68 + c4*4]) = v;
  }

  float sims[16];
  #pragma unroll
  for(int chunk=0; chunk<8; chunk++){
    __syncthreads();
    // load 64x64 chunk of e_norm (1024 float4, 4 per thread)
    #pragma unroll
    for(int q=0; q<4; q++){
      int idx = t + q*256;
      int r = idx >> 4, c4 = idx & 15;
      float4 v = reinterpret_cast<const float4*>(d_enorm)[(chunk*64 + r)*16 + c4];
      *reinterpret_cast<float4*>(&tile[r*68 + c4*4]) = v;
    }
    __syncthreads();
    const float* sr = &srows[w*68];
    float a0 = 0.f, a1 = 0.f;
    #pragma unroll
    for(int kk=0; kk<64; kk+=4){
      float4 s4 = *reinterpret_cast<const float4*>(&sr[kk]);          // broadcast
      float4 e0 = *reinterpret_cast<const float4*>(&tile[lane*68+kk]);
      float4 e1 = *reinterpret_cast<const float4*>(&tile[(lane+32)*68+kk]);
      a0 += s4.x*e0.x + s4.y*e0.y + s4.z*e0.z + s4.w*e0.w;
      a1 += s4.x*e1.x + s4.y*e1.y + s4.z*e1.z + s4.w*e1.w;
    }
    sims[chunk*2]   = a0;   // j = chunk*64 + lane
    sims[chunk*2+1] = a1;   // j = chunk*64 + 32 + lane
  }

  // 20 register-resident warp argmax passes (no block syncs)
  for(int sel=0; sel<Kk; sel++){
    float bv = -INFINITY; int bj = 0x3fffffff;
    #pragma unroll
    for(int s=0; s<16; s++){
      float v = sims[s];
      int j = (s>>1)*64 + (s&1)*32 + lane;
      if(v > bv || (v == bv && j < bj)){ bv = v; bj = j; }
    }
    #pragma unroll
    for(int o=16; o; o>>=1){
      float ov = __shfl_xor_sync(0xffffffffu, bv, o);
      int   oj = __shfl_xor_sync(0xffffffffu, bj, o);
      if(ov > bv || (ov == bv && oj < bj)){ bv = ov; bj = oj; }
    }
    if(lane==0) d_topk[node*Kk+sel] = bj;
    // invalidate winner (its owner lane predicate-clears the slot)
    int wslot = ((bj>>6)<<1) | ((bj>>5)&1);
    bool own = ((bj & 31) == lane);
    #pragma unroll
    for(int s=0; s<16; s++) if(own && s==wslot) sims[s] = -INFINITY;
  }
}

// ---- K3: g = x @ W_lin, plus per-row attention scores s_i, s_j ----
__global__ void k_gemm(const float* __restrict__ x, const float* __restrict__ W,
                       const float* __restrict__ ati, const float* __restrict__ atj){
  __shared__ float Wt[64*68];
  __shared__ float sai[64], saj[64];
  int t = threadIdx.x;
  for(int idx=t; idx<4096; idx+=256){
    int k = idx>>6, c = idx&63;
    Wt[c*68+k] = W[idx];
  }
  if(t < 64){ sai[t]=ati[t]; saj[t]=atj[t]; }
  __syncthreads();
  int lane = t&31, w = t>>5;
  int row  = blockIdx.x*8 + w;
  const float* xr = x + row*64;
  float xv0 = xr[lane], xv1 = xr[32+lane];
  float acc0 = 0.f, acc1 = 0.f;
  #pragma unroll
  for(int kk=0; kk<64; kk+=4){
    float xs = (kk < 32) ? xv0 : xv1;
    float b0 = __shfl_sync(0xffffffffu, xs,  kk   &31);
    float b1 = __shfl_sync(0xffffffffu, xs, (kk+1)&31);
    float b2 = __shfl_sync(0xffffffffu, xs, (kk+2)&31);
    float b3 = __shfl_sync(0xffffffffu, xs, (kk+3)&31);
    float4 wa = *reinterpret_cast<const float4*>(&Wt[lane*68+kk]);
    float4 wb = *reinterpret_cast<const float4*>(&Wt[(lane+32)*68+kk]);
    acc0 += b0*wa.x + b1*wa.y + b2*wa.z + b3*wa.w;
    acc1 += b0*wb.x + b1*wb.y + b2*wb.z + b3*wb.w;
  }
  d_g[row*64+lane]    = acc0;
  d_g[row*64+32+lane] = acc1;
  float si = warpSum(acc0*sai[lane] + acc1*sai[lane+32]);
  float sj = warpSum(acc0*saj[lane] + acc1*saj[lane+32]);
  if(lane==0){
    int node = row & (Nn-1);
    d_si[row] = si + d_eai[node];
    d_sj[row] = sj + d_eaj[node];
  }
}

// ---- K4: softmax over 21 edges + vectorized aggregation + BN1 partials ----
__global__ void k_attn(const float* __restrict__ gnn_bias){
  __shared__ float shs[8*64], shq[8*64];
  int lane = threadIdx.x & 31, w = threadIdx.x >> 5;
  int row  = blockIdx.x*8 + w;
  int b = row >> 9;
  int i = row & (Nn-1);
  int src  = (lane < Kk) ? d_topk[i*Kk+lane] : i;   // lane==20 -> self loop
  int srow = (b << 9) + src;
  float z;
  if(lane <= Kk){
    z = d_si[row] + d_sj[srow];
    z = (z > 0.f) ? z : 0.2f*z;                     // leaky_relu(0.2)
    if(lane < Kk && src == i) z = -INFINITY;        // remove_self_loops
  } else {
    z = -INFINITY;
  }
  float m = warpMax(z);
  float e = (lane <= Kk) ? expf(z - m) : 0.f;
  float s = warpSum(e);
  float attn = e / s;

  // pair-processed gather: lanes 0-15 even edge, 16-31 odd edge; LDG.128 each
  int sub = lane & 15, half = lane >> 4;
  float4 acc = make_float4(0.f,0.f,0.f,0.f);
  #pragma unroll
  for(int p=0; p<11; p++){
    int eidx = 2*p + half;                 // 0..21; edge 21 has attn==0 (lane21)
    float a  = __shfl_sync(0xffffffffu, attn, eidx);
    int   sr = __shfl_sync(0xffffffffu, srow, eidx);
    float4 v = *reinterpret_cast<const float4*>(&d_g[sr*64 + sub*4]);
    acc.x += a*v.x; acc.y += a*v.y; acc.z += a*v.z; acc.w += a*v.w;
  }
  // combine halves
  acc.x += __shfl_xor_sync(0xffffffffu, acc.x, 16);
  acc.y += __shfl_xor_sync(0xffffffffu, acc.y, 16);
  acc.z += __shfl_xor_sync(0xffffffffu, acc.z, 16);
  acc.w += __shfl_xor_sync(0xffffffffu, acc.w, 16);

  if(half == 0){
    float4 bi = *reinterpret_cast<const float4*>(&gnn_bias[sub*4]);
    acc.x += bi.x; acc.y += bi.y; acc.z += bi.z; acc.w += bi.w;
    *reinterpret_cast<float4*>(&d_agg[row*64 + sub*4]) = acc;
    int c0 = sub*4;
    shs[w*64+c0+0]=acc.x; shs[w*64+c0+1]=acc.y; shs[w*64+c0+2]=acc.z; shs[w*64+c0+3]=acc.w;
    shq[w*64+c0+0]=acc.x*acc.x; shq[w*64+c0+1]=acc.y*acc.y;
    shq[w*64+c0+2]=acc.z*acc.z; shq[w*64+c0+3]=acc.w*acc.w;
  }
  __syncthreads();
  int t = threadIdx.x;
  if(t < 64){
    float ps=0.f, pq=0.f;
    #pragma unroll
    for(int ww=0; ww<8; ww++){ ps += shs[ww*64+t]; pq += shq[ww*64+t]; }
    d_ps1[t*ATTN_BLOCKS + blockIdx.x] = ps;
    d_pq1[t*ATTN_BLOCKS + blockIdx.x] = pq;
  }
}

// ---- K5: reduce BN partials -> scale/shift. block per channel. ----
__global__ void k_red(const float* __restrict__ ps, const float* __restrict__ pq,
                      int nblk, const float* __restrict__ gamma,
                      const float* __restrict__ beta,
                      float* __restrict__ scale, float* __restrict__ shift){
  __shared__ float shS[8], shQ[8];
  int c = blockIdx.x, t = threadIdx.x;
  float s = 0.f, q = 0.f;
  for(int idx=t; idx<nblk; idx+=256){
    s += ps[c*nblk+idx];
    q += pq[c*nblk+idx];
  }
  s = warpSum(s); q = warpSum(q);
  if((t&31)==0){ shS[t>>5]=s; shQ[t>>5]=q; }
  __syncthreads();
  if(t==0){
    float S=0.f, Q=0.f;
    #pragma unroll
    for(int ww=0; ww<8; ww++){ S+=shS[ww]; Q+=shQ[ww]; }
    float mu  = S * (1.0f/(float)BN);
    float var = Q * (1.0f/(float)BN) - mu*mu;
    float sc  = gamma[c] * rsqrtf(var + 1e-5f);
    scale[c] = sc;
    shift[c] = beta[c] - mu*sc;
  }
}

// ---- K6: h1 = relu(bn1(agg)) * embed + BN2 partials ----
__global__ void k_h1(const float* __restrict__ embed){
  __shared__ float shp[1024], shq2[1024];
  int t = threadIdx.x;
  int d0 = (t & 15) * 4;
  float4 sc1 = *reinterpret_cast<const float4*>(&d_scale1[d0]);
  float4 sh1 = *reinterpret_cast<const float4*>(&d_shift1[d0]);
  float4 psum = make_float4(0.f,0.f,0.f,0.f);
  float4 psq  = make_float4(0.f,0.f,0.f,0.f);
  #pragma unroll
  for(int q=0; q<4; q++){
    int i = blockIdx.x*1024 + q*256 + t;     // (i&15)==(t&15)
    int row  = i >> 4;
    int node = row & (Nn-1);
    float4 a  = reinterpret_cast<const float4*>(d_agg)[i];
    float4 em = reinterpret_cast<const float4*>(embed)[node*16 + (i&15)];
    float4 r;
    r.x = fmaxf(a.x*sc1.x+sh1.x, 0.f)*em.x;
    r.y = fmaxf(a.y*sc1.y+sh1.y, 0.f)*em.y;
    r.z = fmaxf(a.z*sc1.z+sh1.z, 0.f)*em.z;
    r.w = fmaxf(a.w*sc1.w+sh1.w, 0.f)*em.w;
    reinterpret_cast<float4*>(d_h1)[i] = r;
    psum.x += r.x; psum.y += r.y; psum.z += r.z; psum.w += r.w;
    psq.x += r.x*r.x; psq.y += r.y*r.y; psq.z += r.z*r.z; psq.w += r.w*r.w;
  }
  shp[t*4+0]=psum.x; shp[t*4+1]=psum.y; shp[t*4+2]=psum.z; shp[t*4+3]=psum.w;
  shq2[t*4+0]=psq.x; shq2[t*4+1]=psq.y; shq2[t*4+2]=psq.z; shq2[t*4+3]=psq.w;
  __syncthreads();
  if(t < 64){
    int gi = t >> 2, comp = t & 3;   // float4 slot, component
    float S=0.f, Q=0.f;
    #pragma unroll
    for(int m=0; m<16; m++){
      S += shp [(gi + m*16)*4 + comp];
      Q += shq2[(gi + m*16)*4 + comp];
    }
    d_ps2[t*H1_BLOCKS + blockIdx.x] = S;
    d_pq2[t*H1_BLOCKS + blockIdx.x] = Q;
  }
}

// ---- K7: out = relu(bn2(h1)) @ out_W + out_b, 2 rows per warp ----
__global__ void k_out(const float* __restrict__ outW, const float* __restrict__ outB,
                      float* __restrict__ out){
  int lane = threadIdx.x & 31, w = threadIdx.x >> 5;
  int sub = lane & 15, half = lane >> 4;
  int row = blockIdx.x*16 + w*2 + half;
  float4 v = *reinterpret_cast<const float4*>(&d_h1[row*64 + sub*4]);
  float4 sc = *reinterpret_cast<const float4*>(&d_scale2[sub*4]);
  float4 sh = *reinterpret_cast<const float4*>(&d_shift2[sub*4]);
  float4 ow = *reinterpret_cast<const float4*>(&outW[sub*4]);
  float p = fmaxf(v.x*sc.x+sh.x,0.f)*ow.x + fmaxf(v.y*sc.y+sh.y,0.f)*ow.y
          + fmaxf(v.z*sc.z+sh.z,0.f)*ow.z + fmaxf(v.w*sc.w+sh.w,0.f)*ow.w;
  #pragma unroll
  for(int o=8; o; o>>=1) p += __shfl_xor_sync(0xffffffffu, p, o);
  if(sub==0) out[row] = p + outB[0];
}

extern "C" void kernel_launch(void* const* d_in, const int* in_sizes, int n_in,
                              void* d_out, int out_size){
  int iData, iEmbed, iW, iAtI, iAtJ, iAemI, iAemJ, iBias, iG1, iB1, iG2, iB2, iOW, iOB;
  if(n_in >= 15 && in_sizes[1] == 2048){
    iData=0; iEmbed=2; iW=3; iAtI=4; iAtJ=5; iAemI=6; iAemJ=7; iBias=8;
    iG1=9; iB1=10; iG2=11; iB2=12; iOW=13; iOB=14;
  } else {
    iData=0; iEmbed=1; iW=2; iAtI=3; iAtJ=4; iAemI=5; iAemJ=6; iBias=7;
    iG1=8; iB1=9; iG2=10; iB2=11; iOW=12; iOB=13;
  }
  const float* data  = (const float*)d_in[iData];
  const float* embed = (const float*)d_in[iEmbed];
  const float* W     = (const float*)d_in[iW];
  const float* atI   = (const float*)d_in[iAtI];
  const float* atJ   = (const float*)d_in[iAtJ];
  const float* aemI  = (const float*)d_in[iAemI];
  const float* aemJ  = (const float*)d_in[iAemJ];
  const float* bias  = (const float*)d_in[iBias];
  const float* g1    = (const float*)d_in[iG1];
  const float* b1    = (const float*)d_in[iB1];
  const float* g2    = (const float*)d_in[iG2];
  const float* b2    = (const float*)d_in[iB2];
  const float* outW  = (const float*)d_in[iOW];
  const float* outB  = (const float*)d_in[iOB];
  float* out = (float*)d_out;

  float *sc1, *sh1, *sc2, *sh2, *ps1, *pq1, *ps2, *pq2;
  cudaGetSymbolAddress((void**)&sc1, d_scale1);
  cudaGetSymbolAddress((void**)&sh1, d_shift1);
  cudaGetSymbolAddress((void**)&sc2, d_scale2);
  cudaGetSymbolAddress((void**)&sh2, d_shift2);
  cudaGetSymbolAddress((void**)&ps1, d_ps1);
  cudaGetSymbolAddress((void**)&pq1, d_pq1);
  cudaGetSymbolAddress((void**)&ps2, d_ps2);
  cudaGetSymbolAddress((void**)&pq2, d_pq2);

  k_embed<<<64, 256>>>(embed, aemI, aemJ);
  k_topk <<<64, 256>>>();
  k_gemm <<<BN/8, 256>>>(data, W, atI, atJ);
  k_attn <<<ATTN_BLOCKS, 256>>>(bias);
  k_red  <<<64, 256>>>(ps1, pq1, ATTN_BLOCKS, g1, b1, sc1, sh1);
  k_h1   <<<H1_BLOCKS, 256>>>(embed);
  k_red  <<<64, 256>>>(ps2, pq2, H1_BLOCKS, g2, b2, sc2, sh2);
  k_out  <<<BN/16, 256>>>(outW, outB, out);
}

// round 4
// speedup vs baseline: 3.4369x; 1.5770x over previous
#include <cuda_runtime.h>
#include <math.h>

#define Bsz 128
#define Nn  512
#define Ff  64
#define Dd  64
#define Kk  20
#define BN  (Bsz*Nn)          // 65536
#define NELEM (BN*Dd)         // 4194304
#define ATTN_BLOCKS Bsz       // 128 (one block per batch)
#define H1_BLOCKS   1024

// ---------------- device scratch (no allocations allowed) ----------------
__device__ float d_g[NELEM];
__device__ float d_agg[NELEM];
__device__ float d_h1[NELEM];
__device__ float d_enorm[Nn*Dd];
__device__ float d_si[BN];
__device__ float d_sj[BN];
__device__ float d_eai[Nn];
__device__ float d_eaj[Nn];
__device__ int   d_topk[Nn*Kk];
__device__ float d_ps1[64*ATTN_BLOCKS];   // channel-major BN1 partials
__device__ float d_pq1[64*ATTN_BLOCKS];
__device__ float d_ps2[64*H1_BLOCKS];     // channel-major BN2 partials
__device__ float d_pq2[64*H1_BLOCKS];
__device__ float d_scale1[64], d_shift1[64], d_scale2[64], d_shift2[64];

__device__ __forceinline__ float warpSum(float v){
  #pragma unroll
  for(int o=16;o;o>>=1) v += __shfl_xor_sync(0xffffffffu, v, o);
  return v;
}
__device__ __forceinline__ float warpMax(float v){
  #pragma unroll
  for(int o=16;o;o>>=1) v = fmaxf(v, __shfl_xor_sync(0xffffffffu, v, o));
  return v;
}

// ---- K1: normalize embed rows, per-node embed-attention scalars ----
__global__ void k_embed(const float* __restrict__ embed,
                        const float* __restrict__ aemi,
                        const float* __restrict__ aemj){
  int gw   = (blockIdx.x*blockDim.x + threadIdx.x) >> 5;
  int lane = threadIdx.x & 31;
  if(gw >= Nn) return;
  float v0 = embed[gw*64+lane];
  float v1 = embed[gw*64+32+lane];
  float ss = warpSum(v0*v0 + v1*v1);
  float inv = 1.0f/(sqrtf(ss)+1e-12f);
  d_enorm[gw*64+lane]    = v0*inv;
  d_enorm[gw*64+32+lane] = v1*inv;
  float si = warpSum(v0*aemi[lane] + v1*aemi[lane+32]);
  float sj = warpSum(v0*aemj[lane] + v1*aemj[lane+32]);
  if(lane==0){ d_eai[gw]=si; d_eaj[gw]=sj; }
}

// ---- K2: warp-per-node topk, sims register-resident ----
__global__ void k_topk(){
  __shared__ float tile[64*68];
  __shared__ float srows[8*68];
  int t = threadIdx.x, w = t>>5, lane = t&31;
  int node = blockIdx.x*8 + w;

  if(t < 128){
    int r = t >> 4, c4 = t & 15;
    float4 v = reinterpret_cast<const float4*>(d_enorm)[(blockIdx.x*8 + r)*16 + c4];
    *reinterpret_cast<float4*>(&srows[r*68 + c4*4]) = v;
  }

  float sims[16];
  #pragma unroll
  for(int chunk=0; chunk<8; chunk++){
    __syncthreads();
    #pragma unroll
    for(int q=0; q<4; q++){
      int idx = t + q*256;
      int r = idx >> 4, c4 = idx & 15;
      float4 v = reinterpret_cast<const float4*>(d_enorm)[(chunk*64 + r)*16 + c4];
      *reinterpret_cast<float4*>(&tile[r*68 + c4*4]) = v;
    }
    __syncthreads();
    const float* sr = &srows[w*68];
    float a0 = 0.f, a1 = 0.f;
    #pragma unroll
    for(int kk=0; kk<64; kk+=4){
      float4 s4 = *reinterpret_cast<const float4*>(&sr[kk]);
      float4 e0 = *reinterpret_cast<const float4*>(&tile[lane*68+kk]);
      float4 e1 = *reinterpret_cast<const float4*>(&tile[(lane+32)*68+kk]);
      a0 += s4.x*e0.x + s4.y*e0.y + s4.z*e0.z + s4.w*e0.w;
      a1 += s4.x*e1.x + s4.y*e1.y + s4.z*e1.z + s4.w*e1.w;
    }
    sims[chunk*2]   = a0;
    sims[chunk*2+1] = a1;
  }

  for(int sel=0; sel<Kk; sel++){
    float bv = -INFINITY; int bj = 0x3fffffff;
    #pragma unroll
    for(int s=0; s<16; s++){
      float v = sims[s];
      int j = (s>>1)*64 + (s&1)*32 + lane;
      if(v > bv || (v == bv && j < bj)){ bv = v; bj = j; }
    }
    #pragma unroll
    for(int o=16; o; o>>=1){
      float ov = __shfl_xor_sync(0xffffffffu, bv, o);
      int   oj = __shfl_xor_sync(0xffffffffu, bj, o);
      if(ov > bv || (ov == bv && oj < bj)){ bv = ov; bj = oj; }
    }
    if(lane==0) d_topk[node*Kk+sel] = bj;
    int wslot = ((bj>>6)<<1) | ((bj>>5)&1);
    bool own = ((bj & 31) == lane);
    #pragma unroll
    for(int s=0; s<16; s++) if(own && s==wslot) sims[s] = -INFINITY;
  }
}

// ---- K3: g = x @ W_lin via 64x64x64 register-tiled block, + s_i/s_j ----
// 1024 blocks x 256 threads; each thread computes 4 rows x 4 cols.
__global__ void k_gemm(const float* __restrict__ x, const float* __restrict__ W,
                       const float* __restrict__ ati, const float* __restrict__ atj){
  __shared__ float Ws[64*68];   // Ws[k*68 + col]
  __shared__ float xs[64*68];   // xs[row*68 + k]
  __shared__ float sdi[64*17], sdj[64*17];
  int t = threadIdx.x;
  int tx = t & 15, ty = t >> 4;

  const float4* W4 = reinterpret_cast<const float4*>(W);
  const float4* X4 = reinterpret_cast<const float4*>(x + blockIdx.x*64*64);
  #pragma unroll
  for(int q=0; q<4; q++){
    int idx = q*256 + t;
    int r = idx >> 4, c4 = idx & 15;
    float4 wv = W4[idx];
    *reinterpret_cast<float4*>(&Ws[r*68 + c4*4]) = wv;
    float4 xv = X4[idx];
    *reinterpret_cast<float4*>(&xs[r*68 + c4*4]) = xv;
  }
  __syncthreads();

  float4 acc0 = make_float4(0.f,0.f,0.f,0.f);
  float4 acc1 = make_float4(0.f,0.f,0.f,0.f);
  float4 acc2 = make_float4(0.f,0.f,0.f,0.f);
  float4 acc3 = make_float4(0.f,0.f,0.f,0.f);
  const float* x0 = &xs[(ty*4+0)*68];
  const float* x1 = &xs[(ty*4+1)*68];
  const float* x2 = &xs[(ty*4+2)*68];
  const float* x3 = &xs[(ty*4+3)*68];
  #pragma unroll 16
  for(int k=0; k<64; k++){
    float4 b4 = *reinterpret_cast<const float4*>(&Ws[k*68 + tx*4]);
    float a0 = x0[k], a1 = x1[k], a2 = x2[k], a3 = x3[k];
    acc0.x += a0*b4.x; acc0.y += a0*b4.y; acc0.z += a0*b4.z; acc0.w += a0*b4.w;
    acc1.x += a1*b4.x; acc1.y += a1*b4.y; acc1.z += a1*b4.z; acc1.w += a1*b4.w;
    acc2.x += a2*b4.x; acc2.y += a2*b4.y; acc2.z += a2*b4.z; acc2.w += a2*b4.w;
    acc3.x += a3*b4.x; acc3.y += a3*b4.y; acc3.z += a3*b4.z; acc3.w += a3*b4.w;
  }

  int row0 = blockIdx.x*64 + ty*4;
  *reinterpret_cast<float4*>(&d_g[(row0+0)*64 + tx*4]) = acc0;
  *reinterpret_cast<float4*>(&d_g[(row0+1)*64 + tx*4]) = acc1;
  *reinterpret_cast<float4*>(&d_g[(row0+2)*64 + tx*4]) = acc2;
  *reinterpret_cast<float4*>(&d_g[(row0+3)*64 + tx*4]) = acc3;

  float4 av = *reinterpret_cast<const float4*>(&ati[tx*4]);
  float4 aw = *reinterpret_cast<const float4*>(&atj[tx*4]);
  sdi[(ty*4+0)*17+tx] = acc0.x*av.x+acc0.y*av.y+acc0.z*av.z+acc0.w*av.w;
  sdi[(ty*4+1)*17+tx] = acc1.x*av.x+acc1.y*av.y+acc1.z*av.z+acc1.w*av.w;
  sdi[(ty*4+2)*17+tx] = acc2.x*av.x+acc2.y*av.y+acc2.z*av.z+acc2.w*av.w;
  sdi[(ty*4+3)*17+tx] = acc3.x*av.x+acc3.y*av.y+acc3.z*av.z+acc3.w*av.w;
  sdj[(ty*4+0)*17+tx] = acc0.x*aw.x+acc0.y*aw.y+acc0.z*aw.z+acc0.w*aw.w;
  sdj[(ty*4+1)*17+tx] = acc1.x*aw.x+acc1.y*aw.y+acc1.z*aw.z+acc1.w*aw.w;
  sdj[(ty*4+2)*17+tx] = acc2.x*aw.x+acc2.y*aw.y+acc2.z*aw.z+acc2.w*aw.w;
  sdj[(ty*4+3)*17+tx] = acc3.x*aw.x+acc3.y*aw.y+acc3.z*aw.z+acc3.w*aw.w;
  __syncthreads();
  if(t < 64){
    float si = 0.f, sj = 0.f;
    #pragma unroll
    for(int m=0; m<16; m++){ si += sdi[t*17+m]; sj += sdj[t*17+m]; }
    int grow = blockIdx.x*64 + t;
    int node = grow & (Nn-1);
    d_si[grow] = si + d_eai[node];
    d_sj[grow] = sj + d_eaj[node];
  }
}

// ---- K4: one block per batch; g slice + scores cached in smem ----
__global__ void k_attn(const float* __restrict__ gnn_bias){
  extern __shared__ float sm[];
  float* g_sm  = sm;                 // 32768
  float* sj_sm = sm + 32768;         // 512
  float* si_sm = sm + 33280;         // 512
  int*   tk_sm = (int*)(sm + 33792); // 10240
  __shared__ float rS[16*64], rQ[16*64];

  int t = threadIdx.x;               // 512 threads
  int b = blockIdx.x;

  const float4* gg = reinterpret_cast<const float4*>(d_g) + b*8192;
  float4* g4 = reinterpret_cast<float4*>(g_sm);
  #pragma unroll
  for(int q=0; q<16; q++) g4[q*512+t] = gg[q*512+t];
  sj_sm[t] = d_sj[b*512+t];
  si_sm[t] = d_si[b*512+t];
  #pragma unroll
  for(int q=0; q<20; q++) tk_sm[q*512+t] = d_topk[q*512+t];
  __syncthreads();

  int lane = t & 31, w = t >> 5;
  int sub = lane & 15, half = lane >> 4;
  float4 bi4 = *reinterpret_cast<const float4*>(&gnn_bias[sub*4]);
  float4 ps = make_float4(0.f,0.f,0.f,0.f);
  float4 pq = make_float4(0.f,0.f,0.f,0.f);

  for(int it=0; it<32; it++){
    int i = w*32 + it;
    int src = (lane < Kk) ? tk_sm[i*Kk+lane] : i;
    float z;
    if(lane <= Kk){
      z = si_sm[i] + sj_sm[src];
      z = (z > 0.f) ? z : 0.2f*z;
      if(lane < Kk && src == i) z = -INFINITY;
    } else z = -INFINITY;
    float m = warpMax(z);
    float e = (lane <= Kk) ? expf(z - m) : 0.f;
    float s = warpSum(e);
    float attn = e / s;

    float4 acc = make_float4(0.f,0.f,0.f,0.f);
    #pragma unroll
    for(int p=0; p<11; p++){
      int eidx = 2*p + half;               // 0..21 (21 -> attn 0)
      float a  = __shfl_sync(0xffffffffu, attn, eidx);
      int   sr = __shfl_sync(0xffffffffu, src, eidx);
      float4 v = *reinterpret_cast<const float4*>(&g_sm[sr*64 + sub*4]);
      acc.x += a*v.x; acc.y += a*v.y; acc.z += a*v.z; acc.w += a*v.w;
    }
    acc.x += __shfl_xor_sync(0xffffffffu, acc.x, 16);
    acc.y += __shfl_xor_sync(0xffffffffu, acc.y, 16);
    acc.z += __shfl_xor_sync(0xffffffffu, acc.z, 16);
    acc.w += __shfl_xor_sync(0xffffffffu, acc.w, 16);
    if(half == 0){
      acc.x += bi4.x; acc.y += bi4.y; acc.z += bi4.z; acc.w += bi4.w;
      *reinterpret_cast<float4*>(&d_agg[(b*512+i)*64 + sub*4]) = acc;
      ps.x += acc.x; ps.y += acc.y; ps.z += acc.z; ps.w += acc.w;
      pq.x += acc.x*acc.x; pq.y += acc.y*acc.y; pq.z += acc.z*acc.z; pq.w += acc.w*acc.w;
    }
  }
  if(half == 0){
    int c0 = sub*4;
    rS[w*64+c0+0]=ps.x; rS[w*64+c0+1]=ps.y; rS[w*64+c0+2]=ps.z; rS[w*64+c0+3]=ps.w;
    rQ[w*64+c0+0]=pq.x; rQ[w*64+c0+1]=pq.y; rQ[w*64+c0+2]=pq.z; rQ[w*64+c0+3]=pq.w;
  }
  __syncthreads();
  if(t < 64){
    float S=0.f, Q=0.f;
    #pragma unroll
    for(int ww=0; ww<16; ww++){ S += rS[ww*64+t]; Q += rQ[ww*64+t]; }
    d_ps1[t*ATTN_BLOCKS + b] = S;
    d_pq1[t*ATTN_BLOCKS + b] = Q;
  }
}

// ---- K5: reduce BN partials -> scale/shift. block per channel. ----
__global__ void k_red(const float* __restrict__ ps, const float* __restrict__ pq,
                      int nblk, const float* __restrict__ gamma,
                      const float* __restrict__ beta,
                      float* __restrict__ scale, float* __restrict__ shift){
  __shared__ float shS[8], shQ[8];
  int c = blockIdx.x, t = threadIdx.x;
  float s = 0.f, q = 0.f;
  for(int idx=t; idx<nblk; idx+=256){
    s += ps[c*nblk+idx];
    q += pq[c*nblk+idx];
  }
  s = warpSum(s); q = warpSum(q);
  if((t&31)==0){ shS[t>>5]=s; shQ[t>>5]=q; }
  __syncthreads();
  if(t==0){
    float S=0.f, Q=0.f;
    #pragma unroll
    for(int ww=0; ww<8; ww++){ S+=shS[ww]; Q+=shQ[ww]; }
    float mu  = S * (1.0f/(float)BN);
    float var = Q * (1.0f/(float)BN) - mu*mu;
    float sc  = gamma[c] * rsqrtf(var + 1e-5f);
    scale[c] = sc;
    shift[c] = beta[c] - mu*sc;
  }
}

// ---- K6: h1 = relu(bn1(agg)) * embed + BN2 partials ----
__global__ void k_h1(const float* __restrict__ embed){
  __shared__ float shp[1024], shq2[1024];
  int t = threadIdx.x;
  int d0 = (t & 15) * 4;
  float4 sc1 = *reinterpret_cast<const float4*>(&d_scale1[d0]);
  float4 sh1 = *reinterpret_cast<const float4*>(&d_shift1[d0]);
  float4 psum = make_float4(0.f,0.f,0.f,0.f);
  float4 psq  = make_float4(0.f,0.f,0.f,0.f);
  #pragma unroll
  for(int q=0; q<4; q++){
    int i = blockIdx.x*1024 + q*256 + t;     // (i&15)==(t&15)
    int row  = i >> 4;
    int node = row & (Nn-1);
    float4 a  = reinterpret_cast<const float4*>(d_agg)[i];
    float4 em = reinterpret_cast<const float4*>(embed)[node*16 + (i&15)];
    float4 r;
    r.x = fmaxf(a.x*sc1.x+sh1.x, 0.f)*em.x;
    r.y = fmaxf(a.y*sc1.y+sh1.y, 0.f)*em.y;
    r.z = fmaxf(a.z*sc1.z+sh1.z, 0.f)*em.z;
    r.w = fmaxf(a.w*sc1.w+sh1.w, 0.f)*em.w;
    reinterpret_cast<float4*>(d_h1)[i] = r;
    psum.x += r.x; psum.y += r.y; psum.z += r.z; psum.w += r.w;
    psq.x += r.x*r.x; psq.y += r.y*r.y; psq.z += r.z*r.z; psq.w += r.w*r.w;
  }
  shp[t*4+0]=psum.x; shp[t*4+1]=psum.y; shp[t*4+2]=psum.z; shp[t*4+3]=psum.w;
  shq2[t*4+0]=psq.x; shq2[t*4+1]=psq.y; shq2[t*4+2]=psq.z; shq2[t*4+3]=psq.w;
  __syncthreads();
  if(t < 64){
    int gi = t >> 2, comp = t & 3;
    float S=0.f, Q=0.f;
    #pragma unroll
    for(int m=0; m<16; m++){
      S += shp [(gi + m*16)*4 + comp];
      Q += shq2[(gi + m*16)*4 + comp];
    }
    d_ps2[t*H1_BLOCKS + blockIdx.x] = S;
    d_pq2[t*H1_BLOCKS + blockIdx.x] = Q;
  }
}

// ---- K7: out = relu(bn2(h1)) @ out_W + out_b ----
__global__ void k_out(const float* __restrict__ outW, const float* __restrict__ outB,
                      float* __restrict__ out){
  int lane = threadIdx.x & 31, w = threadIdx.x >> 5;
  int sub = lane & 15, half = lane >> 4;
  int row = blockIdx.x*16 + w*2 + half;
  float4 v = *reinterpret_cast<const float4*>(&d_h1[row*64 + sub*4]);
  float4 sc = *reinterpret_cast<const float4*>(&d_scale2[sub*4]);
  float4 sh = *reinterpret_cast<const float4*>(&d_shift2[sub*4]);
  float4 ow = *reinterpret_cast<const float4*>(&outW[sub*4]);
  float p = fmaxf(v.x*sc.x+sh.x,0.f)*ow.x + fmaxf(v.y*sc.y+sh.y,0.f)*ow.y
          + fmaxf(v.z*sc.z+sh.z,0.f)*ow.z + fmaxf(v.w*sc.w+sh.w,0.f)*ow.w;
  #pragma unroll
  for(int o=8; o; o>>=1) p += __shfl_xor_sync(0xffffffffu, p, o);
  if(sub==0) out[row] = p + outB[0];
}

extern "C" void kernel_launch(void* const* d_in, const int* in_sizes, int n_in,
                              void* d_out, int out_size){
  int iData, iEmbed, iW, iAtI, iAtJ, iAemI, iAemJ, iBias, iG1, iB1, iG2, iB2, iOW, iOB;
  if(n_in >= 15 && in_sizes[1] == 2048){
    iData=0; iEmbed=2; iW=3; iAtI=4; iAtJ=5; iAemI=6; iAemJ=7; iBias=8;
    iG1=9; iB1=10; iG2=11; iB2=12; iOW=13; iOB=14;
  } else {
    iData=0; iEmbed=1; iW=2; iAtI=3; iAtJ=4; iAemI=5; iAemJ=6; iBias=7;
    iG1=8; iB1=9; iG2=10; iB2=11; iOW=12; iOB=13;
  }
  const float* data  = (const float*)d_in[iData];
  const float* embed = (const float*)d_in[iEmbed];
  const float* W     = (const float*)d_in[iW];
  const float* atI   = (const float*)d_in[iAtI];
  const float* atJ   = (const float*)d_in[iAtJ];
  const float* aemI  = (const float*)d_in[iAemI];
  const float* aemJ  = (const float*)d_in[iAemJ];
  const float* bias  = (const float*)d_in[iBias];
  const float* g1    = (const float*)d_in[iG1];
  const float* b1    = (const float*)d_in[iB1];
  const float* g2    = (const float*)d_in[iG2];
  const float* b2    = (const float*)d_in[iB2];
  const float* outW  = (const float*)d_in[iOW];
  const float* outB  = (const float*)d_in[iOB];
  float* out = (float*)d_out;

  float *sc1, *sh1, *sc2, *sh2, *ps1, *pq1, *ps2, *pq2;
  cudaGetSymbolAddress((void**)&sc1, d_scale1);
  cudaGetSymbolAddress((void**)&sh1, d_shift1);
  cudaGetSymbolAddress((void**)&sc2, d_scale2);
  cudaGetSymbolAddress((void**)&sh2, d_shift2);
  cudaGetSymbolAddress((void**)&ps1, d_ps1);
  cudaGetSymbolAddress((void**)&pq1, d_pq1);
  cudaGetSymbolAddress((void**)&ps2, d_ps2);
  cudaGetSymbolAddress((void**)&pq2, d_pq2);

  // g(32768) + sj(512) + si(512) + topk(10240) floats
  const int attn_smem = (32768 + 512 + 512 + 10240) * 4;
  cudaFuncSetAttribute(k_attn, cudaFuncAttributeMaxDynamicSharedMemorySize, attn_smem);

  k_embed<<<64, 256>>>(embed, aemI, aemJ);
  k_topk <<<64, 256>>>();
  k_gemm <<<BN/64, 256>>>(data, W, atI, atJ);
  k_attn <<<ATTN_BLOCKS, 512, attn_smem>>>(bias);
  k_red  <<<64, 256>>>(ps1, pq1, ATTN_BLOCKS, g1, b1, sc1, sh1);
  k_h1   <<<H1_BLOCKS, 256>>>(embed);
  k_red  <<<64, 256>>>(ps2, pq2, H1_BLOCKS, g2, b2, sc2, sh2);
  k_out  <<<BN/16, 256>>>(outW, outB, out);
}

// round 6
// speedup vs baseline: 3.6923x; 1.0743x over previous
#include <cuda_runtime.h>
#include <math.h>

#define Bsz 128
#define Nn  512
#define Ff  64
#define Dd  64
#define Kk  20
#define BN  (Bsz*Nn)          // 65536
#define NELEM (BN*Dd)         // 4194304
#define ATTN_BLOCKS Bsz       // 128 (one block per batch)
#define H1_BLOCKS   1024

// ---------------- device scratch (no allocations allowed) ----------------
__device__ float d_g[NELEM];
__device__ float d_agg[NELEM];
__device__ float d_h1[NELEM];
__device__ float d_enorm[Nn*Dd];
__device__ float d_si[BN];
__device__ float d_sj[BN];
__device__ float d_eai[Nn];
__device__ float d_eaj[Nn];
__device__ int   d_topk[Nn*Kk];
__device__ float d_ps1[64*ATTN_BLOCKS];   // channel-major BN1 partials
__device__ float d_pq1[64*ATTN_BLOCKS];
__device__ float d_ps2[64*H1_BLOCKS];     // channel-major BN2 partials
__device__ float d_pq2[64*H1_BLOCKS];
__device__ float d_scale1[64], d_shift1[64], d_scale2[64], d_shift2[64];

__device__ __forceinline__ float warpSum(float v){
  #pragma unroll
  for(int o=16;o;o>>=1) v += __shfl_xor_sync(0xffffffffu, v, o);
  return v;
}
__device__ __forceinline__ float warpMax(float v){
  #pragma unroll
  for(int o=16;o;o>>=1) v = fmaxf(v, __shfl_xor_sync(0xffffffffu, v, o));
  return v;
}
__device__ __forceinline__ float f4c(const float4& v, int j){
  return j==0 ? v.x : (j==1 ? v.y : (j==2 ? v.z : v.w));
}

// ---- K1: normalize embed rows, per-node embed-attention scalars ----
__global__ void k_embed(const float* __restrict__ embed,
                        const float* __restrict__ aemi,
                        const float* __restrict__ aemj){
  int gw   = (blockIdx.x*blockDim.x + threadIdx.x) >> 5;
  int lane = threadIdx.x & 31;
  if(gw >= Nn) return;
  float v0 = embed[gw*64+lane];
  float v1 = embed[gw*64+32+lane];
  float ss = warpSum(v0*v0 + v1*v1);
  float inv = 1.0f/(sqrtf(ss)+1e-12f);
  d_enorm[gw*64+lane]    = v0*inv;
  d_enorm[gw*64+32+lane] = v1*inv;
  float si = warpSum(v0*aemi[lane] + v1*aemi[lane+32]);
  float sj = warpSum(v0*aemj[lane] + v1*aemj[lane+32]);
  if(lane==0){ d_eai[gw]=si; d_eaj[gw]=sj; }
}

// ---- K2: warp-per-node topk, sims register-resident ----
__global__ void k_topk(){
  __shared__ float tile[64*68];
  __shared__ float srows[8*68];
  int t = threadIdx.x, w = t>>5, lane = t&31;
  int node = blockIdx.x*8 + w;

  if(t < 128){
    int r = t >> 4, c4 = t & 15;
    float4 v = reinterpret_cast<const float4*>(d_enorm)[(blockIdx.x*8 + r)*16 + c4];
    *reinterpret_cast<float4*>(&srows[r*68 + c4*4]) = v;
  }

  float sims[16];
  #pragma unroll
  for(int chunk=0; chunk<8; chunk++){
    __syncthreads();
    #pragma unroll
    for(int q=0; q<4; q++){
      int idx = t + q*256;
      int r = idx >> 4, c4 = idx & 15;
      float4 v = reinterpret_cast<const float4*>(d_enorm)[(chunk*64 + r)*16 + c4];
      *reinterpret_cast<float4*>(&tile[r*68 + c4*4]) = v;
    }
    __syncthreads();
    const float* sr = &srows[w*68];
    float a0 = 0.f, a1 = 0.f;
    #pragma unroll
    for(int kk=0; kk<64; kk+=4){
      float4 s4 = *reinterpret_cast<const float4*>(&sr[kk]);
      float4 e0 = *reinterpret_cast<const float4*>(&tile[lane*68+kk]);
      float4 e1 = *reinterpret_cast<const float4*>(&tile[(lane+32)*68+kk]);
      a0 += s4.x*e0.x + s4.y*e0.y + s4.z*e0.z + s4.w*e0.w;
      a1 += s4.x*e1.x + s4.y*e1.y + s4.z*e1.z + s4.w*e1.w;
    }
    sims[chunk*2]   = a0;
    sims[chunk*2+1] = a1;
  }

  for(int sel=0; sel<Kk; sel++){
    float bv = -INFINITY; int bj = 0x3fffffff;
    #pragma unroll
    for(int s=0; s<16; s++){
      float v = sims[s];
      int j = (s>>1)*64 + (s&1)*32 + lane;
      if(v > bv || (v == bv && j < bj)){ bv = v; bj = j; }
    }
    #pragma unroll
    for(int o=16; o; o>>=1){
      float ov = __shfl_xor_sync(0xffffffffu, bv, o);
      int   oj = __shfl_xor_sync(0xffffffffu, bj, o);
      if(ov > bv || (ov == bv && oj < bj)){ bv = ov; bj = oj; }
    }
    if(lane==0) d_topk[node*Kk+sel] = bj;
    int wslot = ((bj>>6)<<1) | ((bj>>5)&1);
    bool own = ((bj & 31) == lane);
    #pragma unroll
    for(int s=0; s<16; s++) if(own && s==wslot) sims[s] = -INFINITY;
  }
}

// ---- K3: g = x @ W_lin via 64x64x64 register-tiled block, + s_i/s_j ----
__global__ void k_gemm(const float* __restrict__ x, const float* __restrict__ W,
                       const float* __restrict__ ati, const float* __restrict__ atj){
  __shared__ float Ws[64*68];   // Ws[k*68 + col]
  __shared__ float xs[64*68];   // xs[row*68 + k]
  __shared__ float sdi[64*17], sdj[64*17];
  int t = threadIdx.x;
  int tx = t & 15, ty = t >> 4;

  const float4* W4 = reinterpret_cast<const float4*>(W);
  const float4* X4 = reinterpret_cast<const float4*>(x + blockIdx.x*64*64);
  #pragma unroll
  for(int q=0; q<4; q++){
    int idx = q*256 + t;
    int r = idx >> 4, c4 = idx & 15;
    float4 wv = W4[idx];
    *reinterpret_cast<float4*>(&Ws[r*68 + c4*4]) = wv;
    float4 xv = X4[idx];
    *reinterpret_cast<float4*>(&xs[r*68 + c4*4]) = xv;
  }
  __syncthreads();

  float4 acc0 = make_float4(0.f,0.f,0.f,0.f);
  float4 acc1 = make_float4(0.f,0.f,0.f,0.f);
  float4 acc2 = make_float4(0.f,0.f,0.f,0.f);
  float4 acc3 = make_float4(0.f,0.f,0.f,0.f);
  const float* x0 = &xs[(ty*4+0)*68];
  const float* x1 = &xs[(ty*4+1)*68];
  const float* x2 = &xs[(ty*4+2)*68];
  const float* x3 = &xs[(ty*4+3)*68];
  #pragma unroll
  for(int k4=0; k4<16; k4++){
    float4 xa = *reinterpret_cast<const float4*>(&x0[k4*4]);
    float4 xb = *reinterpret_cast<const float4*>(&x1[k4*4]);
    float4 xc = *reinterpret_cast<const float4*>(&x2[k4*4]);
    float4 xd = *reinterpret_cast<const float4*>(&x3[k4*4]);
    #pragma unroll
    for(int j=0; j<4; j++){
      float4 b4 = *reinterpret_cast<const float4*>(&Ws[(k4*4+j)*68 + tx*4]);
      float a0 = f4c(xa,j), a1 = f4c(xb,j), a2 = f4c(xc,j), a3 = f4c(xd,j);
      acc0.x += a0*b4.x; acc0.y += a0*b4.y; acc0.z += a0*b4.z; acc0.w += a0*b4.w;
      acc1.x += a1*b4.x; acc1.y += a1*b4.y; acc1.z += a1*b4.z; acc1.w += a1*b4.w;
      acc2.x += a2*b4.x; acc2.y += a2*b4.y; acc2.z += a2*b4.z; acc2.w += a2*b4.w;
      acc3.x += a3*b4.x; acc3.y += a3*b4.y; acc3.z += a3*b4.z; acc3.w += a3*b4.w;
    }
  }

  int row0 = blockIdx.x*64 + ty*4;
  *reinterpret_cast<float4*>(&d_g[(row0+0)*64 + tx*4]) = acc0;
  *reinterpret_cast<float4*>(&d_g[(row0+1)*64 + tx*4]) = acc1;
  *reinterpret_cast<float4*>(&d_g[(row0+2)*64 + tx*4]) = acc2;
  *reinterpret_cast<float4*>(&d_g[(row0+3)*64 + tx*4]) = acc3;

  float4 av = *reinterpret_cast<const float4*>(&ati[tx*4]);
  float4 aw = *reinterpret_cast<const float4*>(&atj[tx*4]);
  sdi[(ty*4+0)*17+tx] = acc0.x*av.x+acc0.y*av.y+acc0.z*av.z+acc0.w*av.w;
  sdi[(ty*4+1)*17+tx] = acc1.x*av.x+acc1.y*av.y+acc1.z*av.z+acc1.w*av.w;
  sdi[(ty*4+2)*17+tx] = acc2.x*av.x+acc2.y*av.y+acc2.z*av.z+acc2.w*av.w;
  sdi[(ty*4+3)*17+tx] = acc3.x*av.x+acc3.y*av.y+acc3.z*av.z+acc3.w*av.w;
  sdj[(ty*4+0)*17+tx] = acc0.x*aw.x+acc0.y*aw.y+acc0.z*aw.z+acc0.w*aw.w;
  sdj[(ty*4+1)*17+tx] = acc1.x*aw.x+acc1.y*aw.y+acc1.z*aw.z+acc1.w*aw.w;
  sdj[(ty*4+2)*17+tx] = acc2.x*aw.x+acc2.y*aw.y+acc2.z*aw.z+acc2.w*aw.w;
  sdj[(ty*4+3)*17+tx] = acc3.x*aw.x+acc3.y*aw.y+acc3.z*aw.z+acc3.w*aw.w;
  __syncthreads();
  if(t < 64){
    float si = 0.f, sj = 0.f;
    #pragma unroll
    for(int m=0; m<16; m++){ si += sdi[t*17+m]; sj += sdj[t*17+m]; }
    int grow = blockIdx.x*64 + t;
    int node = grow & (Nn-1);
    d_si[grow] = si + d_eai[node];
    d_sj[grow] = sj + d_eaj[node];
  }
}

// ---- K4: one block per batch, 1024 threads (32 warps for TLP) ----
__global__ void __launch_bounds__(1024,1) k_attn(const float* __restrict__ gnn_bias){
  extern __shared__ float sm[];
  float* g_sm  = sm;                 // 32768
  float* sj_sm = sm + 32768;         // 512
  float* si_sm = sm + 33280;         // 512
  int*   tk_sm = (int*)(sm + 33792); // 10240
  __shared__ float rS[32*64], rQ[32*64];

  int t = threadIdx.x;               // 1024 threads
  int b = blockIdx.x;

  const float4* gg = reinterpret_cast<const float4*>(d_g) + b*8192;
  float4* g4 = reinterpret_cast<float4*>(g_sm);
  #pragma unroll
  for(int q=0; q<8; q++) g4[q*1024+t] = gg[q*1024+t];
  if(t < 512){ sj_sm[t] = d_sj[b*512+t]; si_sm[t] = d_si[b*512+t]; }
  #pragma unroll
  for(int q=0; q<10; q++) tk_sm[q*1024+t] = d_topk[q*1024+t];
  __syncthreads();

  int lane = t & 31, w = t >> 5;
  int sub = lane & 15, half = lane >> 4;
  float4 bi4 = *reinterpret_cast<const float4*>(&gnn_bias[sub*4]);
  float4 ps = make_float4(0.f,0.f,0.f,0.f);
  float4 pq = make_float4(0.f,0.f,0.f,0.f);

  for(int it=0; it<16; it++){
    int i = w*16 + it;
    int src = (lane < Kk) ? tk_sm[i*Kk+lane] : i;
    float z;
    if(lane <= Kk){
      z = si_sm[i] + sj_sm[src];
      z = (z > 0.f) ? z : 0.2f*z;
      if(lane < Kk && src == i) z = -INFINITY;
    } else z = -INFINITY;
    float m = warpMax(z);
    float e = (lane <= Kk) ? __expf(z - m) : 0.f;
    float s = warpSum(e);
    float attn = e / s;

    float4 acc = make_float4(0.f,0.f,0.f,0.f);
    #pragma unroll
    for(int p=0; p<11; p++){
      int eidx = 2*p + half;               // 0..21 (21 -> attn 0)
      float a  = __shfl_sync(0xffffffffu, attn, eidx);
      int   sr = __shfl_sync(0xffffffffu, src, eidx);
      float4 v = *reinterpret_cast<const float4*>(&g_sm[sr*64 + sub*4]);
      acc.x += a*v.x; acc.y += a*v.y; acc.z += a*v.z; acc.w += a*v.w;
    }
    acc.x += __shfl_xor_sync(0xffffffffu, acc.x, 16);
    acc.y += __shfl_xor_sync(0xffffffffu, acc.y, 16);
    acc.z += __shfl_xor_sync(0xffffffffu, acc.z, 16);
    acc.w += __shfl_xor_sync(0xffffffffu, acc.w, 16);
    if(half == 0){
      acc.x += bi4.x; acc.y += bi4.y; acc.z += bi4.z; acc.w += bi4.w;
      *reinterpret_cast<float4*>(&d_agg[(b*512+i)*64 + sub*4]) = acc;
      ps.x += acc.x; ps.y += acc.y; ps.z += acc.z; ps.w += acc.w;
      pq.x += acc.x*acc.x; pq.y += acc.y*acc.y; pq.z += acc.z*acc.z; pq.w += acc.w*acc.w;
    }
  }
  if(half == 0){
    int c0 = sub*4;
    rS[w*64+c0+0]=ps.x; rS[w*64+c0+1]=ps.y; rS[w*64+c0+2]=ps.z; rS[w*64+c0+3]=ps.w;
    rQ[w*64+c0+0]=pq.x; rQ[w*64+c0+1]=pq.y; rQ[w*64+c0+2]=pq.z; rQ[w*64+c0+3]=pq.w;
  }
  __syncthreads();
  if(t < 64){
    float S=0.f, Q=0.f;
    #pragma unroll
    for(int ww=0; ww<32; ww++){ S += rS[ww*64+t]; Q += rQ[ww*64+t]; }
    d_ps1[t*ATTN_BLOCKS + b] = S;
    d_pq1[t*ATTN_BLOCKS + b] = Q;
  }
}

// ---- K5: reduce BN partials -> scale/shift. block per channel. ----
__global__ void k_red(const float* __restrict__ ps, const float* __restrict__ pq,
                      int nblk, const float* __restrict__ gamma,
                      const float* __restrict__ beta,
                      float* __restrict__ scale, float* __restrict__ shift){
  __shared__ float shS[8], shQ[8];
  int c = blockIdx.x, t = threadIdx.x;
  float s = 0.f, q = 0.f;
  for(int idx=t; idx<nblk; idx+=256){
    s += ps[c*nblk+idx];
    q += pq[c*nblk+idx];
  }
  s = warpSum(s); q = warpSum(q);
  if((t&31)==0){ shS[t>>5]=s; shQ[t>>5]=q; }
  __syncthreads();
  if(t==0){
    float S=0.f, Q=0.f;
    #pragma unroll
    for(int ww=0; ww<8; ww++){ S+=shS[ww]; Q+=shQ[ww]; }
    float mu  = S * (1.0f/(float)BN);
    float var = Q * (1.0f/(float)BN) - mu*mu;
    float sc  = gamma[c] * rsqrtf(var + 1e-5f);
    scale[c] = sc;
    shift[c] = beta[c] - mu*sc;
  }
}

// ---- K6: h1 = relu(bn1(agg)) * embed + BN2 partials ----
__global__ void k_h1(const float* __restrict__ embed){
  __shared__ float shp[1024], shq2[1024];
  int t = threadIdx.x;
  int d0 = (t & 15) * 4;
  float4 sc1 = *reinterpret_cast<const float4*>(&d_scale1[d0]);
  float4 sh1 = *reinterpret_cast<const float4*>(&d_shift1[d0]);
  float4 psum = make_float4(0.f,0.f,0.f,0.f);
  float4 psq  = make_float4(0.f,0.f,0.f,0.f);
  #pragma unroll
  for(int q=0; q<4; q++){
    int i = blockIdx.x*1024 + q*256 + t;     // (i&15)==(t&15)
    int row  = i >> 4;
    int node = row & (Nn-1);
    float4 a  = reinterpret_cast<const float4*>(d_agg)[i];
    float4 em = reinterpret_cast<const float4*>(embed)[node*16 + (i&15)];
    float4 r;
    r.x = fmaxf(a.x*sc1.x+sh1.x, 0.f)*em.x;
    r.y = fmaxf(a.y*sc1.y+sh1.y, 0.f)*em.y;
    r.z = fmaxf(a.z*sc1.z+sh1.z, 0.f)*em.z;
    r.w = fmaxf(a.w*sc1.w+sh1.w, 0.f)*em.w;
    reinterpret_cast<float4*>(d_h1)[i] = r;
    psum.x += r.x; psum.y += r.y; psum.z += r.z; psum.w += r.w;
    psq.x += r.x*r.x; psq.y += r.y*r.y; psq.z += r.z*r.z; psq.w += r.w*r.w;
  }
  shp[t*4+0]=psum.x; shp[t*4+1]=psum.y; shp[t*4+2]=psum.z; shp[t*4+3]=psum.w;
  shq2[t*4+0]=psq.x; shq2[t*4+1]=psq.y; shq2[t*4+2]=psq.z; shq2[t*4+3]=psq.w;
  __syncthreads();
  if(t < 64){
    int gi = t >> 2, comp = t & 3;
    float S=0.f, Q=0.f;
    #pragma unroll
    for(int m=0; m<16; m++){
      S += shp [(gi + m*16)*4 + comp];
      Q += shq2[(gi + m*16)*4 + comp];
    }
    d_ps2[t*H1_BLOCKS + blockIdx.x] = S;
    d_pq2[t*H1_BLOCKS + blockIdx.x] = Q;
  }
}

// ---- K7: out = relu(bn2(h1)) @ out_W + out_b ----
__global__ void k_out(const float* __restrict__ outW, const float* __restrict__ outB,
                      float* __restrict__ out){
  int lane = threadIdx.x & 31, w = threadIdx.x >> 5;
  int sub = lane & 15, half = lane >> 4;
  int row = blockIdx.x*16 + w*2 + half;
  float4 v = *reinterpret_cast<const float4*>(&d_h1[row*64 + sub*4]);
  float4 sc = *reinterpret_cast<const float4*>(&d_scale2[sub*4]);
  float4 sh = *reinterpret_cast<const float4*>(&d_shift2[sub*4]);
  float4 ow = *reinterpret_cast<const float4*>(&outW[sub*4]);
  float p = fmaxf(v.x*sc.x+sh.x,0.f)*ow.x + fmaxf(v.y*sc.y+sh.y,0.f)*ow.y
          + fmaxf(v.z*sc.z+sh.z,0.f)*ow.z + fmaxf(v.w*sc.w+sh.w,0.f)*ow.w;
  #pragma unroll
  for(int o=8; o; o>>=1) p += __shfl_xor_sync(0xffffffffu, p, o);
  if(sub==0) out[row] = p + outB[0];
}

extern "C" void kernel_launch(void* const* d_in, const int* in_sizes, int n_in,
                              void* d_out, int out_size){
  int iData, iEmbed, iW, iAtI, iAtJ, iAemI, iAemJ, iBias, iG1, iB1, iG2, iB2, iOW, iOB;
  if(n_in >= 15 && in_sizes[1] == 2048){
    iData=0; iEmbed=2; iW=3; iAtI=4; iAtJ=5; iAemI=6; iAemJ=7; iBias=8;
    iG1=9; iB1=10; iG2=11; iB2=12; iOW=13; iOB=14;
  } else {
    iData=0; iEmbed=1; iW=2; iAtI=3; iAtJ=4; iAemI=5; iAemJ=6; iBias=7;
    iG1=8; iB1=9; iG2=10; iB2=11; iOW=12; iOB=13;
  }
  const float* data  = (const float*)d_in[iData];
  const float* embed = (const float*)d_in[iEmbed];
  const float* W     = (const float*)d_in[iW];
  const float* atI   = (const float*)d_in[iAtI];
  const float* atJ   = (const float*)d_in[iAtJ];
  const float* aemI  = (const float*)d_in[iAemI];
  const float* aemJ  = (const float*)d_in[iAemJ];
  const float* bias  = (const float*)d_in[iBias];
  const float* g1    = (const float*)d_in[iG1];
  const float* b1    = (const float*)d_in[iB1];
  const float* g2    = (const float*)d_in[iG2];
  const float* b2    = (const float*)d_in[iB2];
  const float* outW  = (const float*)d_in[iOW];
  const float* outB  = (const float*)d_in[iOB];
  float* out = (float*)d_out;

  float *sc1, *sh1, *sc2, *sh2, *ps1, *pq1, *ps2, *pq2;
  cudaGetSymbolAddress((void**)&sc1, d_scale1);
  cudaGetSymbolAddress((void**)&sh1, d_shift1);
  cudaGetSymbolAddress((void**)&sc2, d_scale2);
  cudaGetSymbolAddress((void**)&sh2, d_shift2);
  cudaGetSymbolAddress((void**)&ps1, d_ps1);
  cudaGetSymbolAddress((void**)&pq1, d_pq1);
  cudaGetSymbolAddress((void**)&ps2, d_ps2);
  cudaGetSymbolAddress((void**)&pq2, d_pq2);

  // g(32768) + sj(512) + si(512) + topk(10240) floats
  const int attn_smem = (32768 + 512 + 512 + 10240) * 4;
  cudaFuncSetAttribute(k_attn, cudaFuncAttributeMaxDynamicSharedMemorySize, attn_smem);

  k_embed<<<64, 256>>>(embed, aemI, aemJ);
  k_topk <<<64, 256>>>();
  k_gemm <<<BN/64, 256>>>(data, W, atI, atJ);
  k_attn <<<ATTN_BLOCKS, 1024, attn_smem>>>(bias);
  k_red  <<<64, 256>>>(ps1, pq1, ATTN_BLOCKS, g1, b1, sc1, sh1);
  k_h1   <<<H1_BLOCKS, 256>>>(embed);
  k_red  <<<64, 256>>>(ps2, pq2, H1_BLOCKS, g2, b2, sc2, sh2);
  k_out  <<<BN/16, 256>>>(outW, outB, out);
}